// round 15
// baseline (speedup 1.0000x reference)
#include <cuda_runtime.h>
#include <math.h>
#include <stdint.h>

// ---------------------------------------------------------------------------
// Problem constants
// ---------------------------------------------------------------------------
#define BATCH 2048
#define SEQ   15
#define CH    1024
#define NH    16
#define HSZ   64
#define MROWS (BATCH * SEQ)          // 30720
#define SCALE 0.125f
#define LN_EPS 1e-5f

// k-pair permutation (within 8-wide groups): logical k -> stored column
__host__ __device__ __forceinline__ int kperm(int k) {
    return (k & ~7) | ((k & 3) << 1) | ((k >> 2) & 1);
}

// ---------------------------------------------------------------------------
// Scratch (static __device__ — no allocations allowed)
// ---------------------------------------------------------------------------
__device__ float g_xj   [(size_t)MROWS * CH];
__device__ float g_xi   [(size_t)MROWS * CH];
__device__ float g_Jqkv [(size_t)MROWS * 3 * CH];
__device__ float g_Iqkv [(size_t)MROWS * 3 * CH];
__device__ float g_attnX[(size_t)MROWS * CH];
__device__ float g_joint[(size_t)MROWS * CH];
__device__ float g_ynorm[(size_t)MROWS * CH];
__device__ float g_hmid [(size_t)MROWS * (CH / 2)];
// transposed+permuted+rounded weights: Wt[N][K]
__device__ float g_WtJ[(size_t)3 * CH * CH];
__device__ float g_WtI[(size_t)3 * CH * CH];
__device__ float g_WtP[(size_t)CH * CH];
__device__ float g_Wt1[(size_t)(CH / 2) * CH];
__device__ float g_Wt2[(size_t)CH * (CH / 2)];

// ---------------------------------------------------------------------------
// Helpers
// ---------------------------------------------------------------------------
__device__ __forceinline__ float f2tf32(float x) {
    unsigned u;
    asm("cvt.rna.tf32.f32 %0, %1;" : "=r"(u) : "f"(x));
    return __uint_as_float(u);
}
__device__ __forceinline__ void mma_tf32(float* c, const unsigned* a, const unsigned* b) {
    asm volatile(
        "mma.sync.aligned.m16n8k8.row.col.f32.tf32.tf32.f32 "
        "{%0,%1,%2,%3}, {%4,%5,%6,%7}, {%8,%9}, {%0,%1,%2,%3};\n"
        : "+f"(c[0]), "+f"(c[1]), "+f"(c[2]), "+f"(c[3])
        : "r"(a[0]), "r"(a[1]), "r"(a[2]), "r"(a[3]), "r"(b[0]), "r"(b[1]));
}
__device__ __forceinline__ unsigned smem_addr_u32(const void* p) {
    return (unsigned)__cvta_generic_to_shared(p);
}
__device__ __forceinline__ void cp_async16(unsigned s, const void* g) {
    asm volatile("cp.async.cg.shared.global [%0], [%1], 16;" :: "r"(s), "l"(g) : "memory");
}
__device__ __forceinline__ void cp_commit() {
    asm volatile("cp.async.commit_group;" ::: "memory");
}
template <int N>
__device__ __forceinline__ void cp_wait() {
    asm volatile("cp.async.wait_group %0;" :: "n"(N) : "memory");
}

// ---------------------------------------------------------------------------
// Weight prep: in[K][N] -> out[N][kperm(K)], rna-rounded to tf32
// ---------------------------------------------------------------------------
__global__ void prep_weights(const float* __restrict__ in, float* __restrict__ out,
                             int K, int N) {
    __shared__ float tile[32][33];
    const int n0 = blockIdx.x * 32, k0 = blockIdx.y * 32;
    const int tx = threadIdx.x, ty = threadIdx.y;
    #pragma unroll
    for (int r = 0; r < 4; r++)
        tile[ty + r * 8][tx] = in[(size_t)(k0 + ty + r * 8) * N + n0 + tx];
    __syncthreads();
    const int pk = k0 + kperm(tx);
    #pragma unroll
    for (int r = 0; r < 4; r++)
        out[(size_t)(n0 + ty + r * 8) * K + pk] = f2tf32(tile[tx][ty + r * 8]);
}

// ---------------------------------------------------------------------------
// LayerNorm: one block (256 thr) per row. Output tf32-rounded AND k-permuted.
// ---------------------------------------------------------------------------
__global__ void ln_kernel(const float* __restrict__ x,
                          const float* __restrict__ g,
                          const float* __restrict__ b,
                          float* __restrict__ out) {
    const int row = blockIdx.x;
    const int t = threadIdx.x;
    const float4* xr = (const float4*)(x + (size_t)row * CH);
    float4 v = xr[t];
    float s1 = v.x + v.y + v.z + v.w;
    float s2 = v.x * v.x + v.y * v.y + v.z * v.z + v.w * v.w;
    #pragma unroll
    for (int o = 16; o; o >>= 1) {
        s1 += __shfl_xor_sync(0xffffffffu, s1, o);
        s2 += __shfl_xor_sync(0xffffffffu, s2, o);
    }
    __shared__ float w1[8], w2[8];
    if ((t & 31) == 0) { w1[t >> 5] = s1; w2[t >> 5] = s2; }
    __syncthreads();
    if (t < 32) {
        s1 = (t < 8) ? w1[t] : 0.0f;
        s2 = (t < 8) ? w2[t] : 0.0f;
        #pragma unroll
        for (int o = 4; o; o >>= 1) {
            s1 += __shfl_xor_sync(0xffffffffu, s1, o);
            s2 += __shfl_xor_sync(0xffffffffu, s2, o);
        }
        if (t == 0) { w1[0] = s1; w2[0] = s2; }
    }
    __syncthreads();
    const float m = w1[0] * (1.0f / CH);
    const float var = w2[0] * (1.0f / CH) - m * m;
    const float r = rsqrtf(var + LN_EPS);
    float4 gv = ((const float4*)g)[t];
    float4 bv = ((const float4*)b)[t];
    float o[4];
    o[0] = (v.x - m) * r * gv.x + bv.x;
    o[1] = (v.y - m) * r * gv.y + bv.y;
    o[2] = (v.z - m) * r * gv.z + bv.z;
    o[3] = (v.w - m) * r * gv.w + bv.w;
    float* orow = out + (size_t)row * CH;
    #pragma unroll
    for (int e = 0; e < 4; e++) orow[kperm(4 * t + e)] = f2tf32(o[e]);
}

// ---------------------------------------------------------------------------
// tf32 GEMM: C[M x Ncols] = A[M x K] * Wt[Ncols x K]^T  (+epilogue)
// A in gmem [M][kperm(K)]; Wt in gmem [N][kperm(K)] (rounded).
// 128x128x32 blocktile, 3-stage cp.async, one sync/iter, 256 thr, 2x4 warps.
// Fragment loads are LDS.64 (k-pair vectorized).
// EPI: 0 = plain, 1 = +bias +resid, 2 = +bias +GELU (tf32, k-permuted out)
// ---------------------------------------------------------------------------
#define BM 128
#define BN 128
#define BK 32
#define TSTRIDE 36                               // both A and B tiles: [128][36]
#define A_STAGE_F (BM * TSTRIDE)                 // 4608 floats
#define STAGE_F (2 * A_STAGE_F)                  // 9216 floats
#define NSTAGE 3
#define GEMM_SMEM (NSTAGE * STAGE_F * 4)         // 110592 bytes

template <int EPI>
__global__ __launch_bounds__(256, 2)
void gemm_tf32(const float* __restrict__ A, const float* __restrict__ Wt,
               float* __restrict__ C, int Ncols, int K,
               const float* __restrict__ bias, const float* __restrict__ resid) {
    extern __shared__ float smem[];

    const int tid  = threadIdx.x;
    const int warp = tid >> 5;
    const int lane = tid & 31;
    const int g = lane >> 2;          // 0..7
    const int t = lane & 3;           // 0..3
    const int wm = (warp >> 2) * 64;
    const int wn = (warp & 3) * 32;

    const int bm = blockIdx.y * BM;
    const int bn = blockIdx.x * BN;

    const float* Abase = A + (size_t)bm * K;
    const float* Bbase = Wt + (size_t)bn * K;

    float acc[4][4][4];
    #pragma unroll
    for (int i = 0; i < 4; i++)
        #pragma unroll
        for (int j = 0; j < 4; j++)
            #pragma unroll
            for (int e = 0; e < 4; e++) acc[i][j][e] = 0.0f;

    const int nkt = K / BK;

    // Both tiles are 128 rows x 32 k-floats = 1024 16B chunks.
    // chunk c: row = c>>3, kcol = (c&7)*4
    const int r0 = tid >> 3,          c0_ = (tid & 7) << 2;
    const int r1 = (tid + 256) >> 3,  c1_ = ((tid + 256) & 7) << 2;
    const int r2 = (tid + 512) >> 3,  c2_ = ((tid + 512) & 7) << 2;
    const int r3 = (tid + 768) >> 3,  c3_ = ((tid + 768) & 7) << 2;

    auto load_stage = [&](int slot, int kt) {
        float* sA = smem + slot * STAGE_F;
        float* sB = sA + A_STAGE_F;
        const int kf = kt * BK;
        cp_async16(smem_addr_u32(sA + r0 * TSTRIDE + c0_), Abase + (size_t)r0 * K + kf + c0_);
        cp_async16(smem_addr_u32(sA + r1 * TSTRIDE + c1_), Abase + (size_t)r1 * K + kf + c1_);
        cp_async16(smem_addr_u32(sA + r2 * TSTRIDE + c2_), Abase + (size_t)r2 * K + kf + c2_);
        cp_async16(smem_addr_u32(sA + r3 * TSTRIDE + c3_), Abase + (size_t)r3 * K + kf + c3_);
        cp_async16(smem_addr_u32(sB + r0 * TSTRIDE + c0_), Bbase + (size_t)r0 * K + kf + c0_);
        cp_async16(smem_addr_u32(sB + r1 * TSTRIDE + c1_), Bbase + (size_t)r1 * K + kf + c1_);
        cp_async16(smem_addr_u32(sB + r2 * TSTRIDE + c2_), Bbase + (size_t)r2 * K + kf + c2_);
        cp_async16(smem_addr_u32(sB + r3 * TSTRIDE + c3_), Bbase + (size_t)r3 * K + kf + c3_);
    };

    load_stage(0, 0); cp_commit();
    load_stage(1, 1); cp_commit();

    int slot = 0;
    for (int kt = 0; kt < nkt; kt++) {
        cp_wait<1>();
        __syncthreads();

        if (kt + 2 < nkt) {
            int ps = slot + 2; if (ps >= NSTAGE) ps -= NSTAGE;
            load_stage(ps, kt + 2);
        }
        cp_commit();

        const float* sA = smem + slot * STAGE_F;
        const float* sB = sA + A_STAGE_F;

        #pragma unroll
        for (int ks = 0; ks < 4; ks++) {
            const int kc = ks * 8 + 2 * t;       // permuted: (t, t+4) adjacent
            unsigned af[4][4], bf[4][2];
            #pragma unroll
            for (int mi = 0; mi < 4; mi++) {
                const int r = wm + mi * 16 + g;
                const float2 lo = *(const float2*)&sA[(r    ) * TSTRIDE + kc];
                const float2 hi = *(const float2*)&sA[(r + 8) * TSTRIDE + kc];
                af[mi][0] = __float_as_uint(lo.x);
                af[mi][1] = __float_as_uint(hi.x);
                af[mi][2] = __float_as_uint(lo.y);
                af[mi][3] = __float_as_uint(hi.y);
            }
            #pragma unroll
            for (int ni = 0; ni < 4; ni++) {
                const int c = wn + ni * 8 + g;
                const float2 bb = *(const float2*)&sB[c * TSTRIDE + kc];
                bf[ni][0] = __float_as_uint(bb.x);
                bf[ni][1] = __float_as_uint(bb.y);
            }
            #pragma unroll
            for (int mi = 0; mi < 4; mi++)
                #pragma unroll
                for (int ni = 0; ni < 4; ni++)
                    mma_tf32(acc[mi][ni], af[mi], bf[ni]);
        }

        if (++slot == NSTAGE) slot = 0;
    }

    // epilogue
    #pragma unroll
    for (int mi = 0; mi < 4; mi++) {
        #pragma unroll
        for (int ni = 0; ni < 4; ni++) {
            const int rr0 = bm + wm + mi * 16 + g;
            const int cc0 = bn + wn + ni * 8 + t * 2;
            float v[4] = {acc[mi][ni][0], acc[mi][ni][1], acc[mi][ni][2], acc[mi][ni][3]};
            const int rr[4] = {rr0, rr0, rr0 + 8, rr0 + 8};
            const int cc[4] = {cc0, cc0 + 1, cc0, cc0 + 1};
            if (EPI != 0) {
                #pragma unroll
                for (int e = 0; e < 4; e++) {
                    v[e] += bias[cc[e]];
                    if (EPI == 1) v[e] += resid[(size_t)rr[e] * Ncols + cc[e]];
                    if (EPI == 2) {
                        v[e] = 0.5f * v[e] * (1.0f + erff(v[e] * 0.70710678118654752f));
                        v[e] = f2tf32(v[e]);
                    }
                }
            }
            if (EPI == 2) {
                // k-permuted scatter (output feeds fc2 as A-operand)
                #pragma unroll
                for (int e = 0; e < 4; e++)
                    C[(size_t)rr[e] * Ncols + kperm(cc[e])] = v[e];
            } else {
                *(float2*)&C[(size_t)rr0       * Ncols + cc0] = make_float2(v[0], v[1]);
                *(float2*)&C[(size_t)(rr0 + 8) * Ncols + cc0] = make_float2(v[2], v[3]);
            }
        }
    }
}

// ---------------------------------------------------------------------------
// Attention: one block (128 thr) per (batch, head).
// Output tf32-rounded AND k-permuted (A-operand of proj GEMM).
// ---------------------------------------------------------------------------
__global__ __launch_bounds__(128)
void attn_kernel(const float* __restrict__ Jqkv, const float* __restrict__ Iqkv,
                 const float* __restrict__ Wc, float* __restrict__ outX) {
    const int bh = blockIdx.x;
    const int b = bh >> 4;
    const int h = bh & 15;
    const int tid = threadIdx.x;

    __shared__ float sJq[SEQ][HSZ + 1], sJk[SEQ][HSZ + 1], sJv[SEQ][HSZ + 1];
    __shared__ float sIq[SEQ][HSZ + 1], sIk[SEQ][HSZ + 1], sIv[SEQ][HSZ + 1];
    __shared__ float sW[HSZ][SEQ];
    __shared__ float sS[SEQ][SEQ + 1];

    const size_t base = (size_t)b * SEQ * (3 * CH) + (size_t)h * HSZ;
    for (int i = tid; i < SEQ * HSZ; i += 128) {
        const int n = i >> 6, d = i & 63;
        const float* jp = Jqkv + base + (size_t)n * (3 * CH) + d;
        sJq[n][d] = jp[0];
        sJk[n][d] = jp[CH];
        sJv[n][d] = jp[2 * CH];
        const float* ip = Iqkv + base + (size_t)n * (3 * CH) + d;
        sIq[n][d] = ip[0];
        sIk[n][d] = ip[CH];
        sIv[n][d] = ip[2 * CH];
    }
    for (int i = tid; i < HSZ * SEQ; i += 128) sW[i / SEQ][i % SEQ] = Wc[i];
    __syncthreads();

    for (int i = tid; i < SEQ * SEQ; i += 128) {
        const int q = i / SEQ, k = i % SEQ;
        float acc = 0.0f, accl = 0.0f;
        #pragma unroll
        for (int d = 0; d < HSZ; d++) {
            acc  += sJq[q][d] * sJk[k][d] + sIq[q][d] * sIk[k][d];
            accl += sIv[q][d] * sW[d][k];
        }
        sS[q][k] = (acc + accl) * SCALE;
    }
    __syncthreads();

    if (tid < SEQ) {
        const int q = tid;
        float mx = -1e30f;
        #pragma unroll
        for (int k = 0; k < SEQ; k++) mx = fmaxf(mx, sS[q][k]);
        float sum = 0.0f;
        #pragma unroll
        for (int k = 0; k < SEQ; k++) { float e = expf(sS[q][k] - mx); sS[q][k] = e; sum += e; }
        const float inv = 1.0f / sum;
        #pragma unroll
        for (int k = 0; k < SEQ; k++) sS[q][k] *= inv;
    }
    __syncthreads();

    for (int i = tid; i < SEQ * HSZ; i += 128) {
        const int q = i >> 6, d = i & 63;
        float acc = 0.0f;
        #pragma unroll
        for (int k = 0; k < SEQ; k++) acc += sS[q][k] * sJv[k][d];
        outX[((size_t)b * SEQ + q) * CH + (size_t)h * HSZ + kperm(d)] = f2tf32(acc);
    }
}

// ---------------------------------------------------------------------------
// Host entry
// ---------------------------------------------------------------------------
extern "C" void kernel_launch(void* const* d_in, const int* in_sizes, int n_in,
                              void* d_out, int out_size) {
    const float* joint_feature    = (const float*)d_in[0];
    const float* relation_feature = (const float*)d_in[1];
    const float* W_Jqkv  = (const float*)d_in[2];
    const float* W_Iqk   = (const float*)d_in[3];
    const float* W_Iconv = (const float*)d_in[4];
    const float* W_proj  = (const float*)d_in[5];
    const float* b_proj  = (const float*)d_in[6];
    const float* g_attn1 = (const float*)d_in[7];
    const float* b_attn1 = (const float*)d_in[8];
    const float* g_attn2 = (const float*)d_in[9];
    const float* b_attn2 = (const float*)d_in[10];
    const float* g_jln   = (const float*)d_in[11];
    const float* b_jln   = (const float*)d_in[12];
    const float* W_fc1   = (const float*)d_in[13];
    const float* b_fc1   = (const float*)d_in[14];
    const float* W_fc2   = (const float*)d_in[15];
    const float* b_fc2   = (const float*)d_in[16];
    float* out = (float*)d_out;

    float *xj, *xi, *Jq, *Iq, *ax, *jt, *yn, *hm;
    float *wtj, *wti, *wtp, *wt1, *wt2;
    cudaGetSymbolAddress((void**)&xj, g_xj);
    cudaGetSymbolAddress((void**)&xi, g_xi);
    cudaGetSymbolAddress((void**)&Jq, g_Jqkv);
    cudaGetSymbolAddress((void**)&Iq, g_Iqkv);
    cudaGetSymbolAddress((void**)&ax, g_attnX);
    cudaGetSymbolAddress((void**)&jt, g_joint);
    cudaGetSymbolAddress((void**)&yn, g_ynorm);
    cudaGetSymbolAddress((void**)&hm, g_hmid);
    cudaGetSymbolAddress((void**)&wtj, g_WtJ);
    cudaGetSymbolAddress((void**)&wti, g_WtI);
    cudaGetSymbolAddress((void**)&wtp, g_WtP);
    cudaGetSymbolAddress((void**)&wt1, g_Wt1);
    cudaGetSymbolAddress((void**)&wt2, g_Wt2);

    cudaFuncSetAttribute(gemm_tf32<0>, cudaFuncAttributeMaxDynamicSharedMemorySize, GEMM_SMEM);
    cudaFuncSetAttribute(gemm_tf32<1>, cudaFuncAttributeMaxDynamicSharedMemorySize, GEMM_SMEM);
    cudaFuncSetAttribute(gemm_tf32<2>, cudaFuncAttributeMaxDynamicSharedMemorySize, GEMM_SMEM);

    // 0) weight prep: transpose + k-permute + tf32 round
    {
        dim3 b32(32, 8);
        prep_weights<<<dim3(3 * CH / 32, CH / 32), b32>>>(W_Jqkv, wtj, CH, 3 * CH);
        prep_weights<<<dim3(3 * CH / 32, CH / 32), b32>>>(W_Iqk,  wti, CH, 3 * CH);
        prep_weights<<<dim3(CH / 32, CH / 32),     b32>>>(W_proj, wtp, CH, CH);
        prep_weights<<<dim3(CH / 2 / 32, CH / 32), b32>>>(W_fc1,  wt1, CH, CH / 2);
        prep_weights<<<dim3(CH / 32, CH / 2 / 32), b32>>>(W_fc2,  wt2, CH / 2, CH);
    }

    // 1) LN both streams (tf32-rounded, k-permuted outputs)
    ln_kernel<<<MROWS, 256>>>(joint_feature,    g_attn1, b_attn1, xj);
    ln_kernel<<<MROWS, 256>>>(relation_feature, g_attn2, b_attn2, xi);

    // 2) QKV projections
    {
        dim3 grid(3 * CH / BN, MROWS / BM);
        gemm_tf32<0><<<grid, 256, GEMM_SMEM>>>(xj, wtj, Jq, 3 * CH, CH, nullptr, nullptr);
        gemm_tf32<0><<<grid, 256, GEMM_SMEM>>>(xi, wti, Iq, 3 * CH, CH, nullptr, nullptr);
    }

    // 3) Attention (tf32-rounded, k-permuted output)
    attn_kernel<<<BATCH * NH, 128>>>(Jq, Iq, W_Iconv, ax);

    // 4) proj + bias + residual -> joint (exact fp32)
    {
        dim3 grid(CH / BN, MROWS / BM);
        gemm_tf32<1><<<grid, 256, GEMM_SMEM>>>(ax, wtp, jt, CH, CH, b_proj, joint_feature);
    }

    // 5) LN(joint) (tf32-rounded, k-permuted output)
    ln_kernel<<<MROWS, 256>>>(jt, g_jln, b_jln, yn);

    // 6) fc1 + bias + GELU (tf32-rounded, k-permuted output)
    {
        dim3 grid((CH / 2) / BN, MROWS / BM);
        gemm_tf32<2><<<grid, 256, GEMM_SMEM>>>(yn, wt1, hm, CH / 2, CH, b_fc1, nullptr);
    }

    // 7) fc2 + bias + residual(joint) -> out (exact fp32)
    {
        dim3 grid(CH / BN, MROWS / BM);
        gemm_tf32<1><<<grid, 256, GEMM_SMEM>>>(hm, wt2, out, CH, CH / 2, b_fc2, jt);
    }
}

// round 16
// speedup vs baseline: 1.1467x; 1.1467x over previous
#include <cuda_runtime.h>
#include <math.h>
#include <stdint.h>

// ---------------------------------------------------------------------------
// Problem constants
// ---------------------------------------------------------------------------
#define BATCH 2048
#define SEQ   15
#define CH    1024
#define NH    16
#define HSZ   64
#define MROWS (BATCH * SEQ)          // 30720
#define SCALE 0.125f
#define LN_EPS 1e-5f

// k-pair permutation (within 8-wide groups): logical k -> stored column.
// Applied ONLY to the B (weight) matrices, at prep time in gmem.
__host__ __device__ __forceinline__ int kperm(int k) {
    return (k & ~7) | ((k & 3) << 1) | ((k >> 2) & 1);
}

// ---------------------------------------------------------------------------
// Scratch (static __device__ — no allocations allowed)
// ---------------------------------------------------------------------------
__device__ float g_xj   [(size_t)MROWS * CH];
__device__ float g_xi   [(size_t)MROWS * CH];
__device__ float g_Jqkv [(size_t)MROWS * 3 * CH];
__device__ float g_Iqkv [(size_t)MROWS * 3 * CH];
__device__ float g_attnX[(size_t)MROWS * CH];
__device__ float g_joint[(size_t)MROWS * CH];
__device__ float g_ynorm[(size_t)MROWS * CH];
__device__ float g_hmid [(size_t)MROWS * (CH / 2)];
// prepped weights: Wt[N][kperm(K)], rna-rounded to tf32
__device__ float g_WtJ[(size_t)3 * CH * CH];
__device__ float g_WtI[(size_t)3 * CH * CH];
__device__ float g_WtP[(size_t)CH * CH];
__device__ float g_Wt1[(size_t)(CH / 2) * CH];
__device__ float g_Wt2[(size_t)CH * (CH / 2)];

// ---------------------------------------------------------------------------
// Helpers
// ---------------------------------------------------------------------------
__device__ __forceinline__ float f2tf32(float x) {
    unsigned u;
    asm("cvt.rna.tf32.f32 %0, %1;" : "=r"(u) : "f"(x));
    return __uint_as_float(u);
}
__device__ __forceinline__ float4 f2tf32_4(float4 v) {
    v.x = f2tf32(v.x); v.y = f2tf32(v.y); v.z = f2tf32(v.z); v.w = f2tf32(v.w);
    return v;
}
__device__ __forceinline__ void mma_tf32(float* c, const unsigned* a, const unsigned* b) {
    asm volatile(
        "mma.sync.aligned.m16n8k8.row.col.f32.tf32.tf32.f32 "
        "{%0,%1,%2,%3}, {%4,%5,%6,%7}, {%8,%9}, {%0,%1,%2,%3};\n"
        : "+f"(c[0]), "+f"(c[1]), "+f"(c[2]), "+f"(c[3])
        : "r"(a[0]), "r"(a[1]), "r"(a[2]), "r"(a[3]), "r"(b[0]), "r"(b[1]));
}
__device__ __forceinline__ unsigned smem_addr_u32(const void* p) {
    return (unsigned)__cvta_generic_to_shared(p);
}
__device__ __forceinline__ void cp_async16(unsigned s, const void* g) {
    asm volatile("cp.async.cg.shared.global [%0], [%1], 16;" :: "r"(s), "l"(g) : "memory");
}
__device__ __forceinline__ void cp_commit() {
    asm volatile("cp.async.commit_group;" ::: "memory");
}
template <int N>
__device__ __forceinline__ void cp_wait() {
    asm volatile("cp.async.wait_group %0;" :: "n"(N) : "memory");
}

// ---------------------------------------------------------------------------
// Weight prep: in[K][N] -> out[N][kperm(K)], rna-rounded to tf32 (gmem-side;
// the k-pair interleave makes the B fragment (t, t+4) pair contiguous).
// ---------------------------------------------------------------------------
__global__ void prep_weights(const float* __restrict__ in, float* __restrict__ out,
                             int K, int N) {
    __shared__ float tile[32][33];
    const int n0 = blockIdx.x * 32, k0 = blockIdx.y * 32;
    const int tx = threadIdx.x, ty = threadIdx.y;
    #pragma unroll
    for (int r = 0; r < 4; r++)
        tile[ty + r * 8][tx] = in[(size_t)(k0 + ty + r * 8) * N + n0 + tx];
    __syncthreads();
    const int pk = k0 + kperm(tx);
    #pragma unroll
    for (int r = 0; r < 4; r++)
        out[(size_t)(n0 + ty + r * 8) * K + pk] = f2tf32(tile[tx][ty + r * 8]);
}

// ---------------------------------------------------------------------------
// LayerNorm: one block (256 thr) per row of 1024. Output tf32-rounded (plain
// layout, vectorized float4 stores).
// ---------------------------------------------------------------------------
__global__ void ln_kernel(const float* __restrict__ x,
                          const float* __restrict__ g,
                          const float* __restrict__ b,
                          float* __restrict__ out) {
    const int row = blockIdx.x;
    const int t = threadIdx.x;
    const float4* xr = (const float4*)(x + (size_t)row * CH);
    float4 v = xr[t];
    float s1 = v.x + v.y + v.z + v.w;
    float s2 = v.x * v.x + v.y * v.y + v.z * v.z + v.w * v.w;
    #pragma unroll
    for (int o = 16; o; o >>= 1) {
        s1 += __shfl_xor_sync(0xffffffffu, s1, o);
        s2 += __shfl_xor_sync(0xffffffffu, s2, o);
    }
    __shared__ float w1[8], w2[8];
    if ((t & 31) == 0) { w1[t >> 5] = s1; w2[t >> 5] = s2; }
    __syncthreads();
    if (t < 32) {
        s1 = (t < 8) ? w1[t] : 0.0f;
        s2 = (t < 8) ? w2[t] : 0.0f;
        #pragma unroll
        for (int o = 4; o; o >>= 1) {
            s1 += __shfl_xor_sync(0xffffffffu, s1, o);
            s2 += __shfl_xor_sync(0xffffffffu, s2, o);
        }
        if (t == 0) { w1[0] = s1; w2[0] = s2; }
    }
    __syncthreads();
    const float m = w1[0] * (1.0f / CH);
    const float var = w2[0] * (1.0f / CH) - m * m;
    const float r = rsqrtf(var + LN_EPS);
    float4 gv = ((const float4*)g)[t];
    float4 bv = ((const float4*)b)[t];
    float4 o;
    o.x = (v.x - m) * r * gv.x + bv.x;
    o.y = (v.y - m) * r * gv.y + bv.y;
    o.z = (v.z - m) * r * gv.z + bv.z;
    o.w = (v.w - m) * r * gv.w + bv.w;
    ((float4*)(out + (size_t)row * CH))[t] = f2tf32_4(o);
}

// ---------------------------------------------------------------------------
// tf32 GEMM: C[M x Ncols] = A[M x K] * Wt[Ncols x K]^T  (+epilogue)
// A: [M][K] plain (pre-rounded by producers). Wt: [N][kperm(K)] (prepped).
// 128x128x32 blocktile, 3-stage cp.async, one sync/iter, 256 thr, 2x4 warps.
// A fragment loads: scalar LDS.32 (conflict-free, stride 36).
// B fragment loads: LDS.64 (k-pair contiguous via prep permutation).
// EPI: 0 = plain, 1 = +bias +resid, 2 = +bias +GELU (tf32 out)
// ---------------------------------------------------------------------------
#define BM 128
#define BN 128
#define BK 32
#define TSTRIDE 36                               // A and B tiles: [128][36]
#define A_STAGE_F (BM * TSTRIDE)                 // 4608 floats
#define STAGE_F (2 * A_STAGE_F)                  // 9216 floats
#define NSTAGE 3
#define GEMM_SMEM (NSTAGE * STAGE_F * 4)         // 110592 bytes

template <int EPI>
__global__ __launch_bounds__(256, 2)
void gemm_tf32(const float* __restrict__ A, const float* __restrict__ Wt,
               float* __restrict__ C, int Ncols, int K,
               const float* __restrict__ bias, const float* __restrict__ resid) {
    extern __shared__ float smem[];

    const int tid  = threadIdx.x;
    const int warp = tid >> 5;
    const int lane = tid & 31;
    const int g = lane >> 2;          // 0..7
    const int t = lane & 3;           // 0..3
    const int wm = (warp >> 2) * 64;
    const int wn = (warp & 3) * 32;

    const int bm = blockIdx.y * BM;
    const int bn = blockIdx.x * BN;

    const float* Abase = A + (size_t)bm * K;
    const float* Bbase = Wt + (size_t)bn * K;

    float acc[4][4][4];
    #pragma unroll
    for (int i = 0; i < 4; i++)
        #pragma unroll
        for (int j = 0; j < 4; j++)
            #pragma unroll
            for (int e = 0; e < 4; e++) acc[i][j][e] = 0.0f;

    const int nkt = K / BK;

    // Both tiles: 128 rows x 32 k-floats = 1024 16B chunks.
    // chunk c: row = c>>3, kcol = (c&7)*4
    const int r0 = tid >> 3,          c0_ = (tid & 7) << 2;
    const int r1 = (tid + 256) >> 3,  c1_ = ((tid + 256) & 7) << 2;
    const int r2 = (tid + 512) >> 3,  c2_ = ((tid + 512) & 7) << 2;
    const int r3 = (tid + 768) >> 3,  c3_ = ((tid + 768) & 7) << 2;

    auto load_stage = [&](int slot, int kt) {
        float* sA = smem + slot * STAGE_F;
        float* sB = sA + A_STAGE_F;
        const int kf = kt * BK;
        cp_async16(smem_addr_u32(sA + r0 * TSTRIDE + c0_), Abase + (size_t)r0 * K + kf + c0_);
        cp_async16(smem_addr_u32(sA + r1 * TSTRIDE + c1_), Abase + (size_t)r1 * K + kf + c1_);
        cp_async16(smem_addr_u32(sA + r2 * TSTRIDE + c2_), Abase + (size_t)r2 * K + kf + c2_);
        cp_async16(smem_addr_u32(sA + r3 * TSTRIDE + c3_), Abase + (size_t)r3 * K + kf + c3_);
        cp_async16(smem_addr_u32(sB + r0 * TSTRIDE + c0_), Bbase + (size_t)r0 * K + kf + c0_);
        cp_async16(smem_addr_u32(sB + r1 * TSTRIDE + c1_), Bbase + (size_t)r1 * K + kf + c1_);
        cp_async16(smem_addr_u32(sB + r2 * TSTRIDE + c2_), Bbase + (size_t)r2 * K + kf + c2_);
        cp_async16(smem_addr_u32(sB + r3 * TSTRIDE + c3_), Bbase + (size_t)r3 * K + kf + c3_);
    };

    load_stage(0, 0); cp_commit();
    load_stage(1, 1); cp_commit();

    int slot = 0;
    for (int kt = 0; kt < nkt; kt++) {
        cp_wait<1>();
        __syncthreads();

        if (kt + 2 < nkt) {
            int ps = slot + 2; if (ps >= NSTAGE) ps -= NSTAGE;
            load_stage(ps, kt + 2);
        }
        cp_commit();

        const float* sA = smem + slot * STAGE_F;
        const float* sB = sA + A_STAGE_F;

        #pragma unroll
        for (int ks = 0; ks < 4; ks++) {
            const int k0 = ks * 8;
            unsigned af[4][4], bf[4][2];
            #pragma unroll
            for (int mi = 0; mi < 4; mi++) {
                const int r = wm + mi * 16 + g;
                af[mi][0] = __float_as_uint(sA[(r    ) * TSTRIDE + k0 + t]);
                af[mi][1] = __float_as_uint(sA[(r + 8) * TSTRIDE + k0 + t]);
                af[mi][2] = __float_as_uint(sA[(r    ) * TSTRIDE + k0 + t + 4]);
                af[mi][3] = __float_as_uint(sA[(r + 8) * TSTRIDE + k0 + t + 4]);
            }
            #pragma unroll
            for (int ni = 0; ni < 4; ni++) {
                const int c = wn + ni * 8 + g;
                // prepped layout: logical (k0+t, k0+t+4) stored at k0+2t, k0+2t+1
                const float2 bb = *(const float2*)&sB[c * TSTRIDE + k0 + 2 * t];
                bf[ni][0] = __float_as_uint(bb.x);
                bf[ni][1] = __float_as_uint(bb.y);
            }
            #pragma unroll
            for (int mi = 0; mi < 4; mi++)
                #pragma unroll
                for (int ni = 0; ni < 4; ni++)
                    mma_tf32(acc[mi][ni], af[mi], bf[ni]);
        }

        if (++slot == NSTAGE) slot = 0;
    }

    // epilogue
    #pragma unroll
    for (int mi = 0; mi < 4; mi++) {
        #pragma unroll
        for (int ni = 0; ni < 4; ni++) {
            const int rr0 = bm + wm + mi * 16 + g;
            const int cc0 = bn + wn + ni * 8 + t * 2;
            float v[4] = {acc[mi][ni][0], acc[mi][ni][1], acc[mi][ni][2], acc[mi][ni][3]};
            const int rr[4] = {rr0, rr0, rr0 + 8, rr0 + 8};
            const int cc[4] = {cc0, cc0 + 1, cc0, cc0 + 1};
            if (EPI != 0) {
                #pragma unroll
                for (int e = 0; e < 4; e++) {
                    v[e] += bias[cc[e]];
                    if (EPI == 1) v[e] += resid[(size_t)rr[e] * Ncols + cc[e]];
                    if (EPI == 2) {
                        v[e] = 0.5f * v[e] * (1.0f + erff(v[e] * 0.70710678118654752f));
                        v[e] = f2tf32(v[e]);   // hm feeds fc2 as A-operand
                    }
                }
            }
            *(float2*)&C[(size_t)rr0       * Ncols + cc0] = make_float2(v[0], v[1]);
            *(float2*)&C[(size_t)(rr0 + 8) * Ncols + cc0] = make_float2(v[2], v[3]);
        }
    }
}

// ---------------------------------------------------------------------------
// Attention: one block (128 thr) per (batch, head). Output tf32-rounded,
// plain layout.
// ---------------------------------------------------------------------------
__global__ __launch_bounds__(128)
void attn_kernel(const float* __restrict__ Jqkv, const float* __restrict__ Iqkv,
                 const float* __restrict__ Wc, float* __restrict__ outX) {
    const int bh = blockIdx.x;
    const int b = bh >> 4;
    const int h = bh & 15;
    const int tid = threadIdx.x;

    __shared__ float sJq[SEQ][HSZ + 1], sJk[SEQ][HSZ + 1], sJv[SEQ][HSZ + 1];
    __shared__ float sIq[SEQ][HSZ + 1], sIk[SEQ][HSZ + 1], sIv[SEQ][HSZ + 1];
    __shared__ float sW[HSZ][SEQ];
    __shared__ float sS[SEQ][SEQ + 1];

    const size_t base = (size_t)b * SEQ * (3 * CH) + (size_t)h * HSZ;
    for (int i = tid; i < SEQ * HSZ; i += 128) {
        const int n = i >> 6, d = i & 63;
        const float* jp = Jqkv + base + (size_t)n * (3 * CH) + d;
        sJq[n][d] = jp[0];
        sJk[n][d] = jp[CH];
        sJv[n][d] = jp[2 * CH];
        const float* ip = Iqkv + base + (size_t)n * (3 * CH) + d;
        sIq[n][d] = ip[0];
        sIk[n][d] = ip[CH];
        sIv[n][d] = ip[2 * CH];
    }
    for (int i = tid; i < HSZ * SEQ; i += 128) sW[i / SEQ][i % SEQ] = Wc[i];
    __syncthreads();

    for (int i = tid; i < SEQ * SEQ; i += 128) {
        const int q = i / SEQ, k = i % SEQ;
        float acc = 0.0f, accl = 0.0f;
        #pragma unroll
        for (int d = 0; d < HSZ; d++) {
            acc  += sJq[q][d] * sJk[k][d] + sIq[q][d] * sIk[k][d];
            accl += sIv[q][d] * sW[d][k];
        }
        sS[q][k] = (acc + accl) * SCALE;
    }
    __syncthreads();

    if (tid < SEQ) {
        const int q = tid;
        float mx = -1e30f;
        #pragma unroll
        for (int k = 0; k < SEQ; k++) mx = fmaxf(mx, sS[q][k]);
        float sum = 0.0f;
        #pragma unroll
        for (int k = 0; k < SEQ; k++) { float e = expf(sS[q][k] - mx); sS[q][k] = e; sum += e; }
        const float inv = 1.0f / sum;
        #pragma unroll
        for (int k = 0; k < SEQ; k++) sS[q][k] *= inv;
    }
    __syncthreads();

    for (int i = tid; i < SEQ * HSZ; i += 128) {
        const int q = i >> 6, d = i & 63;
        float acc = 0.0f;
        #pragma unroll
        for (int k = 0; k < SEQ; k++) acc += sS[q][k] * sJv[k][d];
        outX[((size_t)b * SEQ + q) * CH + (size_t)h * HSZ + d] = f2tf32(acc);
    }
}

// ---------------------------------------------------------------------------
// Host entry
// ---------------------------------------------------------------------------
extern "C" void kernel_launch(void* const* d_in, const int* in_sizes, int n_in,
                              void* d_out, int out_size) {
    const float* joint_feature    = (const float*)d_in[0];
    const float* relation_feature = (const float*)d_in[1];
    const float* W_Jqkv  = (const float*)d_in[2];
    const float* W_Iqk   = (const float*)d_in[3];
    const float* W_Iconv = (const float*)d_in[4];
    const float* W_proj  = (const float*)d_in[5];
    const float* b_proj  = (const float*)d_in[6];
    const float* g_attn1 = (const float*)d_in[7];
    const float* b_attn1 = (const float*)d_in[8];
    const float* g_attn2 = (const float*)d_in[9];
    const float* b_attn2 = (const float*)d_in[10];
    const float* g_jln   = (const float*)d_in[11];
    const float* b_jln   = (const float*)d_in[12];
    const float* W_fc1   = (const float*)d_in[13];
    const float* b_fc1   = (const float*)d_in[14];
    const float* W_fc2   = (const float*)d_in[15];
    const float* b_fc2   = (const float*)d_in[16];
    float* out = (float*)d_out;

    float *xj, *xi, *Jq, *Iq, *ax, *jt, *yn, *hm;
    float *wtj, *wti, *wtp, *wt1, *wt2;
    cudaGetSymbolAddress((void**)&xj, g_xj);
    cudaGetSymbolAddress((void**)&xi, g_xi);
    cudaGetSymbolAddress((void**)&Jq, g_Jqkv);
    cudaGetSymbolAddress((void**)&Iq, g_Iqkv);
    cudaGetSymbolAddress((void**)&ax, g_attnX);
    cudaGetSymbolAddress((void**)&jt, g_joint);
    cudaGetSymbolAddress((void**)&yn, g_ynorm);
    cudaGetSymbolAddress((void**)&hm, g_hmid);
    cudaGetSymbolAddress((void**)&wtj, g_WtJ);
    cudaGetSymbolAddress((void**)&wti, g_WtI);
    cudaGetSymbolAddress((void**)&wtp, g_WtP);
    cudaGetSymbolAddress((void**)&wt1, g_Wt1);
    cudaGetSymbolAddress((void**)&wt2, g_Wt2);

    cudaFuncSetAttribute(gemm_tf32<0>, cudaFuncAttributeMaxDynamicSharedMemorySize, GEMM_SMEM);
    cudaFuncSetAttribute(gemm_tf32<1>, cudaFuncAttributeMaxDynamicSharedMemorySize, GEMM_SMEM);
    cudaFuncSetAttribute(gemm_tf32<2>, cudaFuncAttributeMaxDynamicSharedMemorySize, GEMM_SMEM);

    // 0) weight prep: transpose + k-pair permute + tf32 round (gmem-side)
    {
        dim3 b32(32, 8);
        prep_weights<<<dim3(3 * CH / 32, CH / 32), b32>>>(W_Jqkv, wtj, CH, 3 * CH);
        prep_weights<<<dim3(3 * CH / 32, CH / 32), b32>>>(W_Iqk,  wti, CH, 3 * CH);
        prep_weights<<<dim3(CH / 32, CH / 32),     b32>>>(W_proj, wtp, CH, CH);
        prep_weights<<<dim3(CH / 2 / 32, CH / 32), b32>>>(W_fc1,  wt1, CH, CH / 2);
        prep_weights<<<dim3(CH / 32, CH / 2 / 32), b32>>>(W_fc2,  wt2, CH / 2, CH);
    }

    // 1) LN both streams (tf32-rounded outputs, plain layout)
    ln_kernel<<<MROWS, 256>>>(joint_feature,    g_attn1, b_attn1, xj);
    ln_kernel<<<MROWS, 256>>>(relation_feature, g_attn2, b_attn2, xi);

    // 2) QKV projections
    {
        dim3 grid(3 * CH / BN, MROWS / BM);
        gemm_tf32<0><<<grid, 256, GEMM_SMEM>>>(xj, wtj, Jq, 3 * CH, CH, nullptr, nullptr);
        gemm_tf32<0><<<grid, 256, GEMM_SMEM>>>(xi, wti, Iq, 3 * CH, CH, nullptr, nullptr);
    }

    // 3) Attention (tf32-rounded output, plain layout)
    attn_kernel<<<BATCH * NH, 128>>>(Jq, Iq, W_Iconv, ax);

    // 4) proj + bias + residual -> joint (exact fp32)
    {
        dim3 grid(CH / BN, MROWS / BM);
        gemm_tf32<1><<<grid, 256, GEMM_SMEM>>>(ax, wtp, jt, CH, CH, b_proj, joint_feature);
    }

    // 5) LN(joint) (tf32-rounded output, plain layout)
    ln_kernel<<<MROWS, 256>>>(jt, g_jln, b_jln, yn);

    // 6) fc1 + bias + GELU (tf32-rounded output)
    {
        dim3 grid((CH / 2) / BN, MROWS / BM);
        gemm_tf32<2><<<grid, 256, GEMM_SMEM>>>(yn, wt1, hm, CH / 2, CH, b_fc1, nullptr);
    }

    // 7) fc2 + bias + residual(joint) -> out (exact fp32)
    {
        dim3 grid(CH / BN, MROWS / BM);
        gemm_tf32<1><<<grid, 256, GEMM_SMEM>>>(hm, wt2, out, CH, CH / 2, b_fc2, jt);
    }
}